// round 1
// baseline (speedup 1.0000x reference)
#include <cuda_runtime.h>
#include <math.h>

#define MR 2
#define NE 8
#define CD 1024
#define DD 256
#define BB 32
#define SS 512

typedef unsigned long long u64;

// 32 MB scratch for z = silu(x @ W_down + b). Static __device__ global (no alloc).
__device__ float g_z[(size_t)MR * BB * SS * DD];

__device__ __forceinline__ u64 splat2(float x) {
    u64 r;
    asm("mov.b64 %0, {%1, %1};" : "=l"(r) : "f"(x));
    return r;
}
__device__ __forceinline__ void fma2(u64& d, u64 a, u64 b) {
    // packed fp32x2 FMA (Blackwell): 2x fp32 FFMA throughput vs 3-reg FFMA
    asm("fma.rn.f32x2 %0, %1, %2, %0;" : "+l"(d) : "l"(a), "l"(b));
}
__device__ __forceinline__ float2 lohi(u64 v) {
    float2 r;
    asm("mov.b64 {%0, %1}, %2;" : "=f"(r.x), "=f"(r.y) : "l"(v));
    return r;
}

// ---------------------------------------------------------------------------
// Kernel 1: z[m,b,s,d] = silu(x[b,s,:] @ down_w[m,e,:,:] + down_b[m,e,:])
// block tile: 128 (s-rows) x 256 (all of D). 512 threads, 8x8 thread tile.
// grid: (S/128=4, B=32, M=2)
// ---------------------------------------------------------------------------
__global__ void __launch_bounds__(512, 1)
down_kernel(const float* __restrict__ x, const int* __restrict__ eidx,
            const float* __restrict__ dw, const float* __restrict__ db) {
    __shared__ float As[128][36];   // [row][k], pad 36 to break store conflicts
    __shared__ float Bs[32][256];   // [k][d]

    const int stile = blockIdx.x;
    const int b = blockIdx.y;
    const int m = blockIdx.z;
    const int e = eidx[m * BB + b];
    const int s0 = stile * 128;

    const float* A    = x  + ((size_t)b * SS + s0) * CD;          // [128 x 1024], ld=CD
    const float* Bg   = dw + (size_t)(m * NE + e) * CD * DD;      // [1024 x 256], ld=DD
    const float* bias = db + (size_t)(m * NE + e) * DD;
    float*       Z    = g_z + ((size_t)(m * BB + b) * SS + s0) * DD;

    const int tid = threadIdx.x;
    const int tx = tid & 31;        // 32 column groups * 8 cols = 256
    const int ty = tid >> 5;        // 16 row groups    * 8 rows = 128
    const int row0 = ty * 8, col0 = tx * 8;

    u64 acc[8][4];
    #pragma unroll
    for (int i = 0; i < 8; i++)
        #pragma unroll
        for (int j = 0; j < 4; j++) acc[i][j] = 0ULL;

    for (int kc = 0; kc < CD; kc += 32) {
        // stage A tile (128 x 32): 1024 float4s over 512 threads
        #pragma unroll
        for (int l = 0; l < 2; l++) {
            int f = tid + l * 512;
            int r = f >> 3, kq = (f & 7) << 2;
            float4 v = *reinterpret_cast<const float4*>(A + (size_t)r * CD + kc + kq);
            *reinterpret_cast<float4*>(&As[r][kq]) = v;
        }
        // stage B tile (32 x 256): 2048 float4s over 512 threads
        #pragma unroll
        for (int l = 0; l < 4; l++) {
            int f = tid + l * 512;
            int k = f >> 6, dq = (f & 63) << 2;
            *reinterpret_cast<float4*>(&Bs[k][dq]) =
                *reinterpret_cast<const float4*>(Bg + (size_t)(kc + k) * DD + dq);
        }
        __syncthreads();

        #pragma unroll 4
        for (int k = 0; k < 32; k++) {
            u64 b2[4];
            const u64* bp = reinterpret_cast<const u64*>(&Bs[k][col0]);
            #pragma unroll
            for (int j = 0; j < 4; j++) b2[j] = bp[j];
            u64 a2[8];
            #pragma unroll
            for (int i = 0; i < 8; i++) a2[i] = splat2(As[row0 + i][k]);  // warp-broadcast
            #pragma unroll
            for (int i = 0; i < 8; i++)
                #pragma unroll
                for (int j = 0; j < 4; j++)
                    fma2(acc[i][j], a2[i], b2[j]);
        }
        __syncthreads();
    }

    // epilogue: + bias, silu, write z
    #pragma unroll
    for (int i = 0; i < 8; i++) {
        float* zr = Z + (size_t)(row0 + i) * DD + col0;
        #pragma unroll
        for (int j = 0; j < 4; j++) {
            float2 v = lohi(acc[i][j]);
            float v0 = v.x + bias[col0 + 2 * j];
            float v1 = v.y + bias[col0 + 2 * j + 1];
            v0 = v0 / (1.0f + expf(-v0));
            v1 = v1 / (1.0f + expf(-v1));
            *reinterpret_cast<float2*>(&zr[2 * j]) = make_float2(v0, v1);
        }
    }
}

// ---------------------------------------------------------------------------
// Kernel 2: out[m,b,s,c] = z[m,b,s,:] @ up_w[m,e,:,:]
// block tile: 128 (s-rows) x 256 (c-cols chunk). grid: (16 = 4 ctiles * 4 stiles, 32, 2)
// ---------------------------------------------------------------------------
__global__ void __launch_bounds__(512, 1)
up_kernel(const int* __restrict__ eidx, const float* __restrict__ uw,
          float* __restrict__ out) {
    __shared__ float As[128][36];
    __shared__ float Bs[32][256];

    const int ctile = blockIdx.x >> 2;   // 0..3
    const int stile = blockIdx.x & 3;    // 0..3
    const int b = blockIdx.y;
    const int m = blockIdx.z;
    const int e = eidx[m * BB + b];
    const int s0 = stile * 128, c0 = ctile * 256;

    const float* A  = g_z + ((size_t)(m * BB + b) * SS + s0) * DD;     // [128 x 256], ld=DD
    const float* Bg = uw  + (size_t)(m * NE + e) * DD * CD;            // [256 x 1024], ld=CD
    float*       O  = out + ((size_t)(m * BB + b) * SS + s0) * CD + c0;

    const int tid = threadIdx.x;
    const int tx = tid & 31;
    const int ty = tid >> 5;
    const int row0 = ty * 8, col0 = tx * 8;

    u64 acc[8][4];
    #pragma unroll
    for (int i = 0; i < 8; i++)
        #pragma unroll
        for (int j = 0; j < 4; j++) acc[i][j] = 0ULL;

    for (int kc = 0; kc < DD; kc += 32) {
        #pragma unroll
        for (int l = 0; l < 2; l++) {
            int f = tid + l * 512;
            int r = f >> 3, kq = (f & 7) << 2;
            float4 v = *reinterpret_cast<const float4*>(A + (size_t)r * DD + kc + kq);
            *reinterpret_cast<float4*>(&As[r][kq]) = v;
        }
        #pragma unroll
        for (int l = 0; l < 4; l++) {
            int f = tid + l * 512;
            int k = f >> 6, dq = (f & 63) << 2;
            *reinterpret_cast<float4*>(&Bs[k][dq]) =
                *reinterpret_cast<const float4*>(Bg + (size_t)(kc + k) * CD + c0 + dq);
        }
        __syncthreads();

        #pragma unroll 4
        for (int k = 0; k < 32; k++) {
            u64 b2[4];
            const u64* bp = reinterpret_cast<const u64*>(&Bs[k][col0]);
            #pragma unroll
            for (int j = 0; j < 4; j++) b2[j] = bp[j];
            u64 a2[8];
            #pragma unroll
            for (int i = 0; i < 8; i++) a2[i] = splat2(As[row0 + i][k]);
            #pragma unroll
            for (int i = 0; i < 8; i++)
                #pragma unroll
                for (int j = 0; j < 4; j++)
                    fma2(acc[i][j], a2[i], b2[j]);
        }
        __syncthreads();
    }

    #pragma unroll
    for (int i = 0; i < 8; i++) {
        float* orow = O + (size_t)(row0 + i) * CD + col0;
        #pragma unroll
        for (int j = 0; j < 4; j++) {
            float2 v = lohi(acc[i][j]);
            *reinterpret_cast<float2*>(&orow[2 * j]) = v;
        }
    }
}

extern "C" void kernel_launch(void* const* d_in, const int* in_sizes, int n_in,
                              void* d_out, int out_size) {
    const float* x    = (const float*)d_in[0];   // [B,S,C]
    const int*   eidx = (const int*)d_in[1];     // [M,B]
    const float* dw   = (const float*)d_in[2];   // [M,N,C,D]
    const float* db   = (const float*)d_in[3];   // [M,N,D]
    const float* uw   = (const float*)d_in[4];   // [M,N,D,C]
    float*       out  = (float*)d_out;           // [M,B,S,C]

    down_kernel<<<dim3(SS / 128, BB, MR), 512>>>(x, eidx, dw, db);
    up_kernel<<<dim3((SS / 128) * (CD / 256), BB, MR), 512>>>(eidx, uw, out);
}

// round 3
// speedup vs baseline: 2.3579x; 2.3579x over previous
#include <cuda_runtime.h>
#include <cuda_bf16.h>
#include <math.h>
#include <stdint.h>

#define MR 2
#define NE 8
#define CD 1024
#define DD 256
#define BB 32
#define SS 512
#define STAGES 3
#define STAGE_BYTES 32768   // Ah 8K | Al 8K | Bh 8K | Bl 8K
#define SMEM_TOTAL (STAGES * STAGE_BYTES)

typedef __nv_bfloat16 bf16;

// ---------------- static device scratch (no allocs) ----------------
__device__ bf16 g_x_h[(size_t)BB * SS * CD];
__device__ bf16 g_x_l[(size_t)BB * SS * CD];
__device__ bf16 g_z_h[(size_t)MR * BB * SS * DD];
__device__ bf16 g_z_l[(size_t)MR * BB * SS * DD];
__device__ bf16 g_dwT_h[(size_t)MR * NE * DD * CD];
__device__ bf16 g_dwT_l[(size_t)MR * NE * DD * CD];
__device__ bf16 g_uwT_h[(size_t)MR * NE * CD * DD];
__device__ bf16 g_uwT_l[(size_t)MR * NE * CD * DD];

// ---------------- ptx helpers ----------------
__device__ __forceinline__ uint32_t smem_u32(const void* p) {
    uint32_t a;
    asm("{ .reg .u64 t; cvta.to.shared.u64 t, %1; cvt.u32.u64 %0, t; }" : "=r"(a) : "l"(p));
    return a;
}
#define CP16(dst, src) \
    asm volatile("cp.async.cg.shared.global [%0], [%1], 16;" :: "r"(dst), "l"(src))
#define CP_COMMIT() asm volatile("cp.async.commit_group;")
#define CP_WAIT1()  asm volatile("cp.async.wait_group 1;")
#define CP_WAIT0()  asm volatile("cp.async.wait_group 0;")

#define LDSM4(r, a) \
    asm volatile("ldmatrix.sync.aligned.m8n8.x4.shared.b16 {%0,%1,%2,%3}, [%4];" \
        : "=r"((r)[0]), "=r"((r)[1]), "=r"((r)[2]), "=r"((r)[3]) : "r"(a))

#define MMA(d, a, b0, b1) \
    asm volatile("mma.sync.aligned.m16n8k16.row.col.f32.bf16.bf16.f32 " \
        "{%0,%1,%2,%3},{%4,%5,%6,%7},{%8,%9},{%0,%1,%2,%3};" \
        : "+f"((d)[0]), "+f"((d)[1]), "+f"((d)[2]), "+f"((d)[3]) \
        : "r"((a)[0]), "r"((a)[1]), "r"((a)[2]), "r"((a)[3]), "r"(b0), "r"(b1))

// XOR swizzle: 128 rows x 32 bf16 (64B rows, 4 x 16B chunks); conflict-free ldmatrix
__device__ __forceinline__ uint32_t swz(uint32_t row, uint32_t chunk) {
    return row * 64u + ((chunk ^ ((row >> 1) & 3u)) << 4);
}

// ---------------- stage loader: 8x cp.async(16B) per thread ----------------
__device__ __forceinline__ void stage_load(uint32_t sbase,
                                           const bf16* __restrict__ Ah,
                                           const bf16* __restrict__ Al, int lda,
                                           const bf16* __restrict__ Bh,
                                           const bf16* __restrict__ Bl, int ldb,
                                           int kc, int tid) {
    #pragma unroll
    for (int i = 0; i < 2; i++) {
        int q = tid + (i << 8);        // 512 chunks: 128 rows x 4 chunks
        int r = q >> 2, c = q & 3;
        uint32_t so = swz(r, c);
        size_t ao = (size_t)r * lda + kc + c * 8;
        size_t bo = (size_t)r * ldb + kc + c * 8;
        CP16(sbase + so,          Ah + ao);
        CP16(sbase + so + 8192,   Al + ao);
        CP16(sbase + so + 16384,  Bh + bo);
        CP16(sbase + so + 24576,  Bl + bo);
    }
}

// ---------------- GEMM mainloop: acc[4][4][4] = split-bf16(A[128xK] @ B^T[128xK]) --
__device__ __forceinline__ void gemm_main(uint32_t smem_b,
                                          const bf16* __restrict__ Ah,
                                          const bf16* __restrict__ Al, int lda,
                                          const bf16* __restrict__ Bh,
                                          const bf16* __restrict__ Bl, int ldb,
                                          int nk, float acc[4][4][4], int tid) {
    const int lane = tid & 31, warp = tid >> 5;
    const int wm = (warp & 1) * 64, wn = (warp >> 1) * 32;

    // prologue: stages 0,1
    stage_load(smem_b, Ah, Al, lda, Bh, Bl, ldb, 0, tid);  CP_COMMIT();
    stage_load(smem_b + STAGE_BYTES, Ah, Al, lda, Bh, Bl, ldb, 32, tid);  CP_COMMIT();

    const int r15 = lane & 15, chi = lane >> 4;

    for (int k = 0; k < nk; k++) {
        if (k + 2 < nk) { CP_WAIT1(); } else { CP_WAIT0(); }
        __syncthreads();
        if (k + 2 < nk) {
            stage_load(smem_b + ((k + 2) % STAGES) * STAGE_BYTES,
                       Ah, Al, lda, Bh, Bl, ldb, (k + 2) * 32, tid);
            CP_COMMIT();
        }
        uint32_t sb = smem_b + (k % STAGES) * STAGE_BYTES;
        #pragma unroll
        for (int ks = 0; ks < 2; ks++) {
            const uint32_t ch = ks * 2 + chi;
            uint32_t bh[2][4], bl[2][4], ah[4][4], al[4][4];
            #pragma unroll
            for (int bt = 0; bt < 2; bt++) {
                uint32_t ab = sb + 16384 + swz(wn + bt * 16 + r15, ch);
                LDSM4(bh[bt], ab);
                LDSM4(bl[bt], ab + 8192);
            }
            #pragma unroll
            for (int mt = 0; mt < 4; mt++) {
                uint32_t aa = sb + swz(wm + mt * 16 + r15, ch);
                LDSM4(ah[mt], aa);
                LDSM4(al[mt], aa + 8192);
            }
            #pragma unroll
            for (int mt = 0; mt < 4; mt++)
                #pragma unroll
                for (int nt = 0; nt < 4; nt++) {
                    const int b2 = nt >> 1, s = nt & 1;
                    MMA(acc[mt][nt], ah[mt], bh[b2][s], bh[b2][2 + s]);
                    MMA(acc[mt][nt], ah[mt], bl[b2][s], bl[b2][2 + s]);
                    MMA(acc[mt][nt], al[mt], bh[b2][s], bh[b2][2 + s]);
                }
        }
        __syncthreads();
    }
}

// ---------------- down: z = silu(x @ dw + db), z stored bf16 hi/lo -----------
__global__ void __launch_bounds__(256)
down_mma(const int* __restrict__ eidx, const float* __restrict__ db) {
    extern __shared__ char smem[];
    uint32_t smem_b = smem_u32(smem);
    const int tid = threadIdx.x, lane = tid & 31, warp = tid >> 5;
    const int wm = (warp & 1) * 64, wn = (warp >> 1) * 32;
    const int stile = blockIdx.x >> 1, ntile = blockIdx.x & 1;
    const int b = blockIdx.y, m = blockIdx.z;
    const int e = eidx[m * BB + b];

    const bf16* Ah = g_x_h + ((size_t)b * SS + stile * 128) * CD;
    const bf16* Al = g_x_l + ((size_t)b * SS + stile * 128) * CD;
    const bf16* Bh = g_dwT_h + (size_t)(m * NE + e) * DD * CD + (size_t)(ntile * 128) * CD;
    const bf16* Bl = g_dwT_l + (size_t)(m * NE + e) * DD * CD + (size_t)(ntile * 128) * CD;

    float acc[4][4][4];
    #pragma unroll
    for (int i = 0; i < 4; i++)
        #pragma unroll
        for (int j = 0; j < 4; j++)
            #pragma unroll
            for (int q = 0; q < 4; q++) acc[i][j][q] = 0.f;

    gemm_main(smem_b, Ah, Al, CD, Bh, Bl, CD, CD / 32, acc, tid);

    const float* bias = db + (size_t)(m * NE + e) * DD;
    const size_t zrow0 = ((size_t)(m * BB + b) * SS + stile * 128);
    const int r0 = lane >> 2, cp = 2 * (lane & 3);

    #pragma unroll
    for (int mt = 0; mt < 4; mt++) {
        #pragma unroll
        for (int nt = 0; nt < 4; nt++) {
            const int col = ntile * 128 + wn + nt * 8 + cp;
            const float2 bv = *reinterpret_cast<const float2*>(bias + col);
            #pragma unroll
            for (int h = 0; h < 2; h++) {   // two row halves (r0, r0+8)
                float v0 = acc[mt][nt][2 * h + 0] + bv.x;
                float v1 = acc[mt][nt][2 * h + 1] + bv.y;
                v0 = v0 / (1.f + __expf(-v0));
                v1 = v1 / (1.f + __expf(-v1));
                bf16 h0 = __float2bfloat16(v0), h1 = __float2bfloat16(v1);
                bf16 l0 = __float2bfloat16(v0 - __bfloat162float(h0));
                bf16 l1 = __float2bfloat16(v1 - __bfloat162float(h1));
                const size_t off = (zrow0 + wm + mt * 16 + r0 + h * 8) * DD + col;
                __nv_bfloat162 hp; hp.x = h0; hp.y = h1;
                __nv_bfloat162 lp; lp.x = l0; lp.y = l1;
                *reinterpret_cast<__nv_bfloat162*>(g_z_h + off) = hp;
                *reinterpret_cast<__nv_bfloat162*>(g_z_l + off) = lp;
            }
        }
    }
}

// ---------------- up: out = z @ uw (fp32 out) --------------------------------
__global__ void __launch_bounds__(256)
up_mma(const int* __restrict__ eidx, float* __restrict__ out) {
    extern __shared__ char smem[];
    uint32_t smem_b = smem_u32(smem);
    const int tid = threadIdx.x, lane = tid & 31, warp = tid >> 5;
    const int wm = (warp & 1) * 64, wn = (warp >> 1) * 32;
    const int stile = blockIdx.x & 3, ctile = blockIdx.x >> 2;
    const int b = blockIdx.y, m = blockIdx.z;
    const int e = eidx[m * BB + b];

    const bf16* Ah = g_z_h + ((size_t)(m * BB + b) * SS + stile * 128) * DD;
    const bf16* Al = g_z_l + ((size_t)(m * BB + b) * SS + stile * 128) * DD;
    const bf16* Bh = g_uwT_h + (size_t)(m * NE + e) * CD * DD + (size_t)(ctile * 128) * DD;
    const bf16* Bl = g_uwT_l + (size_t)(m * NE + e) * CD * DD + (size_t)(ctile * 128) * DD;

    float acc[4][4][4];
    #pragma unroll
    for (int i = 0; i < 4; i++)
        #pragma unroll
        for (int j = 0; j < 4; j++)
            #pragma unroll
            for (int q = 0; q < 4; q++) acc[i][j][q] = 0.f;

    gemm_main(smem_b, Ah, Al, DD, Bh, Bl, DD, DD / 32, acc, tid);

    const size_t orow0 = ((size_t)(m * BB + b) * SS + stile * 128);
    const int r0 = lane >> 2, cp = 2 * (lane & 3);

    #pragma unroll
    for (int mt = 0; mt < 4; mt++) {
        #pragma unroll
        for (int nt = 0; nt < 4; nt++) {
            const int col = ctile * 128 + wn + nt * 8 + cp;
            #pragma unroll
            for (int h = 0; h < 2; h++) {
                const size_t off = (orow0 + wm + mt * 16 + r0 + h * 8) * CD + col;
                *reinterpret_cast<float2*>(out + off) =
                    make_float2(acc[mt][nt][2 * h + 0], acc[mt][nt][2 * h + 1]);
            }
        }
    }
}

// ---------------- prep: split x fp32 -> bf16 hi/lo ---------------------------
__global__ void __launch_bounds__(256)
x_split(const float* __restrict__ x) {
    size_t i = (size_t)blockIdx.x * 256 + threadIdx.x;   // one float4 each
    float4 v = reinterpret_cast<const float4*>(x)[i];
    float f[4] = {v.x, v.y, v.z, v.w};
    __nv_bfloat162 hp[2], lp[2];
    #pragma unroll
    for (int j = 0; j < 2; j++) {
        bf16 h0 = __float2bfloat16(f[2 * j]), h1 = __float2bfloat16(f[2 * j + 1]);
        hp[j].x = h0; hp[j].y = h1;
        lp[j].x = __float2bfloat16(f[2 * j] - __bfloat162float(h0));
        lp[j].y = __float2bfloat16(f[2 * j + 1] - __bfloat162float(h1));
    }
    reinterpret_cast<__nv_bfloat162*>(g_x_h)[i * 2]     = hp[0];
    reinterpret_cast<__nv_bfloat162*>(g_x_h)[i * 2 + 1] = hp[1];
    reinterpret_cast<__nv_bfloat162*>(g_x_l)[i * 2]     = lp[0];
    reinterpret_cast<__nv_bfloat162*>(g_x_l)[i * 2 + 1] = lp[1];
}

// ---------------- prep: transpose [R x Cc] fp32 -> [Cc x R] bf16 hi/lo -------
__global__ void transpose_cvt(const float* __restrict__ in,
                              bf16* __restrict__ oh, bf16* __restrict__ ol,
                              int R, int Cc) {
    __shared__ float t[32][33];
    const size_t mat = blockIdx.z;
    const float* src = in + mat * (size_t)R * Cc;
    bf16* dh = oh + mat * (size_t)R * Cc;
    bf16* dl = ol + mat * (size_t)R * Cc;
    int c0 = blockIdx.x * 32, r0 = blockIdx.y * 32;
    #pragma unroll
    for (int i = threadIdx.y; i < 32; i += 8)
        t[i][threadIdx.x] = src[(size_t)(r0 + i) * Cc + c0 + threadIdx.x];
    __syncthreads();
    #pragma unroll
    for (int i = threadIdx.y; i < 32; i += 8) {
        float v = t[threadIdx.x][i];
        bf16 h = __float2bfloat16(v);
        size_t o = (size_t)(c0 + i) * R + r0 + threadIdx.x;
        dh[o] = h;
        dl[o] = __float2bfloat16(v - __bfloat162float(h));
    }
}

// ---------------- launch ------------------------------------------------------
extern "C" void kernel_launch(void* const* d_in, const int* in_sizes, int n_in,
                              void* d_out, int out_size) {
    const float* x    = (const float*)d_in[0];   // [B,S,C]
    const int*   eidx = (const int*)d_in[1];     // [M,B]
    const float* dw   = (const float*)d_in[2];   // [M,N,C,D]
    const float* db   = (const float*)d_in[3];   // [M,N,D]
    const float* uw   = (const float*)d_in[4];   // [M,N,D,C]
    float*       out  = (float*)d_out;           // [M,B,S,C]

    bf16 *dwt_h, *dwt_l, *uwt_h, *uwt_l;
    cudaGetSymbolAddress((void**)&dwt_h, g_dwT_h);
    cudaGetSymbolAddress((void**)&dwt_l, g_dwT_l);
    cudaGetSymbolAddress((void**)&uwt_h, g_uwT_h);
    cudaGetSymbolAddress((void**)&uwt_l, g_uwT_l);

    cudaFuncSetAttribute(down_mma, cudaFuncAttributeMaxDynamicSharedMemorySize, SMEM_TOTAL);
    cudaFuncSetAttribute(up_mma,   cudaFuncAttributeMaxDynamicSharedMemorySize, SMEM_TOTAL);

    // preps
    x_split<<<(BB * SS * CD / 4) / 256, 256>>>(x);
    transpose_cvt<<<dim3(DD / 32, CD / 32, MR * NE), dim3(32, 8)>>>(dw, dwt_h, dwt_l, CD, DD);
    transpose_cvt<<<dim3(CD / 32, DD / 32, MR * NE), dim3(32, 8)>>>(uw, uwt_h, uwt_l, DD, CD);

    // GEMMs
    down_mma<<<dim3((SS / 128) * (DD / 128), BB, MR), 256, SMEM_TOTAL>>>(eidx, db);
    up_mma<<<dim3((SS / 128) * (CD / 128), BB, MR), 256, SMEM_TOTAL>>>(eidx, out);
}